// round 9
// baseline (speedup 1.0000x reference)
#include <cuda_runtime.h>
#include <math.h>
#include <stdint.h>

#define TT 32768
#define D  128

__device__ float d_LE[64*512*128];
__device__ float d_LD[64*512*128];
__device__ float d_Qe[64*512*128];
__device__ float d_Qd[64*512*128];
__device__ float d_SRCe[16*513*128];
__device__ float d_SRCd[16*513*128];
__device__ float d_Ke[16*513*128];
__device__ float d_Ve[16*513*128];
__device__ float d_Kd[16*513*128];
__device__ float d_Vd[16*513*128];
__device__ float d_S[64*512*513];
__device__ float d_FeatE[64*512*128];
__device__ float d_FeatD[64*512*128];
__device__ float d_Flat[TT*128];
__device__ unsigned long long d_X1[TT*128];
__device__ unsigned long long d_X2[TT*128];
__device__ float d_LastH[64*128];

__device__ __forceinline__ uint32_t smem_u32(const void* p) {
    uint32_t a;
    asm("{ .reg .u64 t; cvta.to.shared.u64 t, %1; cvt.u32.u64 %0, t; }" : "=r"(a) : "l"(p));
    return a;
}
__device__ __forceinline__ uint32_t ctarank() {
    uint32_t r; asm("mov.u32 %0, %%cluster_ctarank;" : "=r"(r)); return r;
}
__device__ __forceinline__ uint32_t mapa_r(uint32_t addr, uint32_t rank) {
    uint32_t r; asm("mapa.shared::cluster.u32 %0, %1, %2;" : "=r"(r) : "r"(addr), "r"(rank));
    return r;
}
__device__ __forceinline__ void st_cluster_u64(uint32_t raddr, unsigned long long v) {
    asm volatile("st.shared::cluster.b64 [%0], %1;" :: "r"(raddr), "l"(v) : "memory");
}
__device__ __forceinline__ unsigned long long ld_vol_shared_u64(uint32_t addr) {
    unsigned long long v;
    asm volatile("ld.volatile.shared.b64 %0, [%1];" : "=l"(v) : "r"(addr) : "memory");
    return v;
}
__device__ __forceinline__ void st_vol_shared_u64(uint32_t addr, unsigned long long v) {
    asm volatile("st.volatile.shared.b64 [%0], %1;" :: "r"(addr), "l"(v) : "memory");
}
__device__ __forceinline__ int ld_acq_cta_shared(uint32_t addr) {
    int v;
    asm volatile("ld.acquire.cta.shared.b32 %0, [%1];" : "=r"(v) : "r"(addr) : "memory");
    return v;
}
__device__ __forceinline__ void st_rel_cta_shared(uint32_t addr, int v) {
    asm volatile("st.release.cta.shared.b32 [%0], %1;" :: "r"(addr), "r"(v) : "memory");
}
__device__ __forceinline__ unsigned long long ld_vol_global_u64(const unsigned long long* p) {
    unsigned long long v;
    asm volatile("ld.volatile.global.b64 %0, [%1];" : "=l"(v) : "l"(p) : "memory");
    return v;
}
__device__ __forceinline__ void st_vol_global_u64(unsigned long long* p, unsigned long long v) {
    asm volatile("st.volatile.global.b64 [%0], %1;" :: "l"(p), "l"(v) : "memory");
}
__device__ __forceinline__ void cluster_sync_() {
    asm volatile("barrier.cluster.arrive.aligned;" ::: "memory");
    asm volatile("barrier.cluster.wait.aligned;" ::: "memory");
}
__device__ __forceinline__ unsigned long long pk2(float a, float b) {
    unsigned long long r;
    asm("mov.b64 %0, {%1, %2};" : "=l"(r) : "f"(a), "f"(b));
    return r;
}
__device__ __forceinline__ void fma2(unsigned long long& acc, unsigned long long a, unsigned long long b) {
    asm("fma.rn.f32x2 %0, %1, %2, %0;" : "+l"(acc) : "l"(a), "l"(b));
}
__device__ __forceinline__ float upk_sum(unsigned long long v) {
    float lo, hi;
    asm("mov.b64 {%0, %1}, %2;" : "=f"(lo), "=f"(hi) : "l"(v));
    return lo + hi;
}
__device__ __forceinline__ float pkt_val(unsigned long long p) {
    return __uint_as_float((unsigned)(p >> 32));
}
__device__ __forceinline__ unsigned pkt_tag(unsigned long long p) {
    return (unsigned)p;
}
__device__ __forceinline__ unsigned long long mk_pkt(unsigned tag, float v) {
    return ((unsigned long long)__float_as_uint(v) << 32) | (unsigned long long)tag;
}
__device__ __forceinline__ float tanh_ap(float x) {
    float y; asm("tanh.approx.f32 %0, %1;" : "=f"(y) : "f"(x)); return y;
}
__device__ __forceinline__ float sig_ap(float x) {
    return 0.5f * tanh_ap(0.5f * x) + 0.5f;
}

__global__ void gemm_k(const float* __restrict__ A, const float* __restrict__ B,
                       float* __restrict__ C, const float* __restrict__ bias,
                       int M, int N, int K, int lda, int ldb, int ldc,
                       long long sA, int divA, long long sB, int divB, long long sC,
                       float alpha, int transB, int accum)
{
    int bz = blockIdx.z;
    const float* Ab = A + (long long)(bz / divA) * sA;
    const float* Bb = B + (long long)(bz / divB) * sB;
    float*       Cb = C + (long long)bz * sC;

    int m0 = blockIdx.y * 64, n0 = blockIdx.x * 64;
    int tx = threadIdx.x, ty = threadIdx.y;
    int tid = ty * 16 + tx;

    __shared__ float As[16][64];
    __shared__ float Bs[16][64];

    float acc[4][4];
#pragma unroll
    for (int i = 0; i < 4; i++)
#pragma unroll
        for (int j = 0; j < 4; j++) acc[i][j] = 0.f;

    for (int k0 = 0; k0 < K; k0 += 16) {
#pragma unroll
        for (int e = 0; e < 4; e++) {
            int idx = tid + 256 * e;
            int kk = idx & 15, m = idx >> 4;
            int gm = m0 + m, gk = k0 + kk;
            As[kk][m] = (gm < M && gk < K) ? Ab[(long long)gm * lda + gk] : 0.f;
        }
        if (transB) {
#pragma unroll
            for (int e = 0; e < 4; e++) {
                int idx = tid + 256 * e;
                int kk = idx & 15, n = idx >> 4;
                int gn = n0 + n, gk = k0 + kk;
                Bs[kk][n] = (gn < N && gk < K) ? Bb[(long long)gn * ldb + gk] : 0.f;
            }
        } else {
#pragma unroll
            for (int e = 0; e < 4; e++) {
                int idx = tid + 256 * e;
                int n = idx & 63, kk = idx >> 6;
                int gn = n0 + n, gk = k0 + kk;
                Bs[kk][n] = (gn < N && gk < K) ? Bb[(long long)gk * ldb + gn] : 0.f;
            }
        }
        __syncthreads();
#pragma unroll
        for (int kk = 0; kk < 16; kk++) {
            float4 a4 = *(const float4*)&As[kk][ty * 4];
            float4 b4 = *(const float4*)&Bs[kk][tx * 4];
            acc[0][0] += a4.x * b4.x; acc[0][1] += a4.x * b4.y; acc[0][2] += a4.x * b4.z; acc[0][3] += a4.x * b4.w;
            acc[1][0] += a4.y * b4.x; acc[1][1] += a4.y * b4.y; acc[1][2] += a4.y * b4.z; acc[1][3] += a4.y * b4.w;
            acc[2][0] += a4.z * b4.x; acc[2][1] += a4.z * b4.y; acc[2][2] += a4.z * b4.z; acc[2][3] += a4.z * b4.w;
            acc[3][0] += a4.w * b4.x; acc[3][1] += a4.w * b4.y; acc[3][2] += a4.w * b4.z; acc[3][3] += a4.w * b4.w;
        }
        __syncthreads();
    }

#pragma unroll
    for (int i = 0; i < 4; i++) {
        int gm = m0 + ty * 4 + i;
        if (gm >= M) continue;
#pragma unroll
        for (int j = 0; j < 4; j++) {
            int gn = n0 + tx * 4 + j;
            if (gn >= N) continue;
            float v = alpha * acc[i][j] + (bias ? bias[gn] : 0.f);
            long long off = (long long)gm * ldc + gn;
            Cb[off] = accum ? (Cb[off] + v) : v;
        }
    }
}

__global__ void softmax_rows(float* __restrict__ S, int n)
{
    float* row = S + (long long)blockIdx.x * n;
    int tid = threadIdx.x;
    __shared__ float red[128];

    float m = -1e30f;
    for (int i = tid; i < n; i += 128) m = fmaxf(m, row[i]);
    red[tid] = m; __syncthreads();
    for (int off = 64; off; off >>= 1) { if (tid < off) red[tid] = fmaxf(red[tid], red[tid + off]); __syncthreads(); }
    float mx = red[0]; __syncthreads();

    float s = 0.f;
    for (int i = tid; i < n; i += 128) { float e = expf(row[i] - mx); row[i] = e; s += e; }
    red[tid] = s; __syncthreads();
    for (int off = 64; off; off >>= 1) { if (tid < off) red[tid] += red[tid + off]; __syncthreads(); }
    float inv = 1.f / red[0];
    __syncthreads();
    for (int i = tid; i < n; i += 128) row[i] *= inv;
}

__global__ void fill_pf(const float* __restrict__ pf)
{
    int sb = blockIdx.x, d = threadIdx.x;
    float v = 1e-5f * pf[sb * 128 + d];
    d_SRCe[(long long)sb * 513 * 128 + d] = v;
    d_SRCd[(long long)sb * 513 * 128 + d] = v;
}

// Sequential 3-layer LSTM; tagged-packet dataflow, no barriers in the loop.
// hslot AND xslot are parity double-buffered (single-buffer xslot deadlocked:
// warp 1 could overwrite tag t+1 with t+2 before lagging warps consumed it).
__global__ void __launch_bounds__(512, 1) __cluster_dims__(4, 1, 1) lstm_kernel(
    const float* __restrict__ G0,
    const float* __restrict__ W_ih,
    const float* __restrict__ W_hh,
    const float* __restrict__ b_ih,
    const float* __restrict__ b_hh)
{
    const int l   = blockIdx.x >> 2;
    const uint32_t c = ctarank();
    const int tid  = threadIdx.x;
    const int j    = tid >> 4;
    const int s    = tid & 15;
    const int w    = tid >> 5;
    const int lane = tid & 31;
    const int J    = (int)c * 32 + j;

    unsigned long long whh[4][4], wih[4][4];
#pragma unroll
    for (int G = 0; G < 4; G++) {
        int R = l * 512 + G * 128 + J;
#pragma unroll
        for (int q = 0; q < 4; q++) {
            float2 wv = *(const float2*)&W_hh[(long long)R * 128 + 8 * s + 2 * q];
            whh[G][q] = pk2(wv.x, wv.y);
        }
    }
    if (l > 0) {
#pragma unroll
        for (int G = 0; G < 4; G++) {
            int R = l * 512 + G * 128 + J;
#pragma unroll
            for (int q = 0; q < 4; q++) {
                float2 wv = *(const float2*)&W_ih[(long long)R * 128 + 8 * s + 2 * q];
                wih[G][q] = pk2(wv.x, wv.y);
            }
        }
    }

    __shared__ __align__(16) unsigned long long hslot[2][128];
    __shared__ __align__(16) unsigned long long xslot[2][128];
    __shared__ __align__(16) float4 sh_gate[32];
    __shared__ int sh_gtag[32];

    if (tid < 128) {
        hslot[0][tid] = mk_pkt(0u, 0.f);
        hslot[1][tid] = mk_pkt(0x80000000u, 0.f);
        xslot[0][tid] = mk_pkt(0x80000000u, 0.f);
        xslot[1][tid] = mk_pkt(0x80000000u, 0.f);
    }
    if (tid < 32) sh_gtag[tid] = 0;
    __syncthreads();
    cluster_sync_();

    const uint32_t hbase = smem_u32(&hslot[0][0]);
    const uint32_t xbase = smem_u32(&xslot[0][0]);
    const uint32_t tbase = smem_u32(&sh_gtag[0]);

    const unsigned long long* Xin  = (l == 1) ? d_X1 : d_X2;
    unsigned long long*       Xout = (l == 0) ? d_X1 : d_X2;

    const int J0 = (int)c * 32 + lane;
    float bias0[4] = {0.f, 0.f, 0.f, 0.f};
    float g0r[4]   = {0.f, 0.f, 0.f, 0.f};
    float cst = 0.f;
    if (w == 0) {
#pragma unroll
        for (int G = 0; G < 4; G++) {
            int R = l * 512 + G * 128 + J0;
            bias0[G] = b_hh[R] + (l > 0 ? b_ih[R] : 0.f);
        }
        if (l == 0) {
#pragma unroll
            for (int G = 0; G < 4; G++) g0r[G] = __ldg(&G0[G * 128 + J0]);
        }
    }

    unsigned long long xr[4] = {0ull, 0ull, 0ull, 0ull};

    for (int t = 0; t < TT; t++) {
        // A. warp 1 forwards x_t into xslot[t&1] (l>0)
        if (l > 0 && w == 1) {
            const unsigned want = (unsigned)(t + 1);
            const unsigned long long* xp = Xin + (long long)t * 128 + 4 * lane;
            for (;;) {
                unsigned mt = pkt_tag(xr[0]) & pkt_tag(xr[1]) & pkt_tag(xr[2]) & pkt_tag(xr[3]);
                unsigned ot = pkt_tag(xr[0]) | pkt_tag(xr[1]) | pkt_tag(xr[2]) | pkt_tag(xr[3]);
                if (mt == want && ot == want) break;
                xr[0] = ld_vol_global_u64(xp + 0);
                xr[1] = ld_vol_global_u64(xp + 1);
                xr[2] = ld_vol_global_u64(xp + 2);
                xr[3] = ld_vol_global_u64(xp + 3);
            }
            uint32_t a = xbase + (uint32_t)((((t & 1) << 7) + 4 * lane) * 8);
            st_vol_shared_u64(a + 0,  xr[0]);
            st_vol_shared_u64(a + 8,  xr[1]);
            st_vol_shared_u64(a + 16, xr[2]);
            st_vol_shared_u64(a + 24, xr[3]);
            if (t + 1 < TT) {
                const unsigned long long* xn = Xin + (long long)(t + 1) * 128 + 4 * lane;
                xr[0] = ld_vol_global_u64(xn + 0);
                xr[1] = ld_vol_global_u64(xn + 1);
                xr[2] = ld_vol_global_u64(xn + 2);
                xr[3] = ld_vol_global_u64(xn + 3);
            }
        }

        // B. poll h slots (local), hh matvec
        unsigned long long hq[4];
        {
            const uint32_t base = hbase + (uint32_t)((((t & 1) << 7) + 8 * s) * 8);
            const unsigned want = (unsigned)t;
            unsigned long long r0, r1, r2, r3, r4, r5, r6, r7;
            for (;;) {
                r0 = ld_vol_shared_u64(base + 0);  r1 = ld_vol_shared_u64(base + 8);
                r2 = ld_vol_shared_u64(base + 16); r3 = ld_vol_shared_u64(base + 24);
                r4 = ld_vol_shared_u64(base + 32); r5 = ld_vol_shared_u64(base + 40);
                r6 = ld_vol_shared_u64(base + 48); r7 = ld_vol_shared_u64(base + 56);
                unsigned mt = pkt_tag(r0) & pkt_tag(r1) & pkt_tag(r2) & pkt_tag(r3)
                            & pkt_tag(r4) & pkt_tag(r5) & pkt_tag(r6) & pkt_tag(r7);
                unsigned ot = pkt_tag(r0) | pkt_tag(r1) | pkt_tag(r2) | pkt_tag(r3)
                            | pkt_tag(r4) | pkt_tag(r5) | pkt_tag(r6) | pkt_tag(r7);
                if (mt == want && ot == want) break;
            }
            hq[0] = pk2(pkt_val(r0), pkt_val(r1));
            hq[1] = pk2(pkt_val(r2), pkt_val(r3));
            hq[2] = pk2(pkt_val(r4), pkt_val(r5));
            hq[3] = pk2(pkt_val(r6), pkt_val(r7));
        }
        unsigned long long acc[4] = {0ull, 0ull, 0ull, 0ull};
#pragma unroll
        for (int G = 0; G < 4; G++) {
            fma2(acc[G], whh[G][0], hq[0]);
            fma2(acc[G], whh[G][1], hq[1]);
            fma2(acc[G], whh[G][2], hq[2]);
            fma2(acc[G], whh[G][3], hq[3]);
        }

        // C. poll x slots (local, parity t&1), ih matvec (l>0)
        if (l > 0) {
            const uint32_t base = xbase + (uint32_t)((((t & 1) << 7) + 8 * s) * 8);
            const unsigned want = (unsigned)(t + 1);
            unsigned long long r0, r1, r2, r3, r4, r5, r6, r7;
            for (;;) {
                r0 = ld_vol_shared_u64(base + 0);  r1 = ld_vol_shared_u64(base + 8);
                r2 = ld_vol_shared_u64(base + 16); r3 = ld_vol_shared_u64(base + 24);
                r4 = ld_vol_shared_u64(base + 32); r5 = ld_vol_shared_u64(base + 40);
                r6 = ld_vol_shared_u64(base + 48); r7 = ld_vol_shared_u64(base + 56);
                unsigned mt = pkt_tag(r0) & pkt_tag(r1) & pkt_tag(r2) & pkt_tag(r3)
                            & pkt_tag(r4) & pkt_tag(r5) & pkt_tag(r6) & pkt_tag(r7);
                unsigned ot = pkt_tag(r0) | pkt_tag(r1) | pkt_tag(r2) | pkt_tag(r3)
                            | pkt_tag(r4) | pkt_tag(r5) | pkt_tag(r6) | pkt_tag(r7);
                if (mt == want && ot == want) break;
            }
            unsigned long long xq0 = pk2(pkt_val(r0), pkt_val(r1));
            unsigned long long xq1 = pk2(pkt_val(r2), pkt_val(r3));
            unsigned long long xq2 = pk2(pkt_val(r4), pkt_val(r5));
            unsigned long long xq3 = pk2(pkt_val(r6), pkt_val(r7));
#pragma unroll
            for (int G = 0; G < 4; G++) {
                fma2(acc[G], wih[G][0], xq0);
                fma2(acc[G], wih[G][1], xq1);
                fma2(acc[G], wih[G][2], xq2);
                fma2(acc[G], wih[G][3], xq3);
            }
        }

        // D. butterfly over 16 k-lanes
        float g[4];
#pragma unroll
        for (int G = 0; G < 4; G++) g[G] = upk_sum(acc[G]);
#pragma unroll
        for (int m = 1; m < 16; m <<= 1) {
#pragma unroll
            for (int G = 0; G < 4; G++)
                g[G] += __shfl_xor_sync(0xffffffffu, g[G], m);
        }

        // E. s==0 lanes publish gates
        if (s == 0) {
            sh_gate[j] = make_float4(g[0], g[1], g[2], g[3]);
            st_rel_cta_shared(tbase + (uint32_t)(j * 4), t + 1);
        }

        // F. warp 0: gather gates, cell, pushes
        if (w == 0) {
            const int want = t + 1;
            int v;
            do { v = ld_acq_cta_shared(tbase + (uint32_t)(lane * 4)); } while (v != want);
            float4 gg = sh_gate[lane];

            float gi = gg.x + bias0[0] + g0r[0];
            float gf = gg.y + bias0[1] + g0r[1];
            float gc = gg.z + bias0[2] + g0r[2];
            float go = gg.w + bias0[3] + g0r[3];

            float si = sig_ap(gi), sf = sig_ap(gf), so = sig_ap(go);
            cst = sf * cst + si * tanh_ap(gc);
            float h = so * tanh_ap(cst);

            unsigned long long pkt = mk_pkt((unsigned)(t + 1), h);
            uint32_t la = hbase + (uint32_t)(((((t + 1) & 1) << 7) + J0) * 8);
            st_cluster_u64(mapa_r(la, 0), pkt);
            st_cluster_u64(mapa_r(la, 1), pkt);
            st_cluster_u64(mapa_r(la, 2), pkt);
            st_cluster_u64(mapa_r(la, 3), pkt);

            if (l < 2) {
                st_vol_global_u64(&Xout[(long long)t * 128 + J0], pkt);
            } else if (t >= TT - 64) {
                d_LastH[(t - (TT - 64)) * 128 + J0] = h;
            }
            if (l == 0 && t + 1 < TT) {
#pragma unroll
                for (int G = 0; G < 4; G++)
                    g0r[G] = __ldg(&G0[(long long)(t + 1) * 512 + G * 128 + J0]);
            }
        }
    }
    cluster_sync_();
}

__global__ void fc_kernel(const float* __restrict__ W1, const float* __restrict__ b1,
                          const float* __restrict__ W2, const float* __restrict__ b2,
                          float* __restrict__ out)
{
    int b = blockIdx.x, tid = threadIdx.x;
    __shared__ float sh[128];
    __shared__ float red[128];
    sh[tid] = d_LastH[b * 128 + tid];
    __syncthreads();
    float s = b1[tid];
    const float* w = W1 + tid * 128;
#pragma unroll 4
    for (int k = 0; k < 128; k++) s += w[k] * sh[k];
    s = fmaxf(s, 0.f) * W2[tid];
    red[tid] = s; __syncthreads();
    for (int off = 64; off; off >>= 1) { if (tid < off) red[tid] += red[tid + off]; __syncthreads(); }
    if (tid == 0) out[b] = 1.f / (1.f + expf(-(red[0] + b2[0])));
}

static void launch_gemm(const float* A, const float* B, float* C, const float* bias,
                        int M, int N, int K, int lda, int ldb, int ldc,
                        long long sA, int divA, long long sB, int divB, long long sC,
                        int batch, float alpha, int transB, int accum)
{
    dim3 grid((N + 63) / 64, (M + 63) / 64, batch), blk(16, 16);
    gemm_k<<<grid, blk>>>(A, B, C, bias, M, N, K, lda, ldb, ldc,
                          sA, divA, sB, divB, sC, alpha, transB, accum);
}

template <typename T>
static float* sym_addr(const T& s)
{
    void* p = nullptr;
    cudaGetSymbolAddress(&p, s);
    return (float*)p;
}

extern "C" void kernel_launch(void* const* d_in, const int* in_sizes, int n_in,
                              void* d_out, int out_size)
{
    const float* sp_emo = (const float*)d_in[0];
    const float* li_emo = (const float*)d_in[1];
    const float* sp_3d  = (const float*)d_in[2];
    const float* li_3d  = (const float*)d_in[3];
    const float* pf     = (const float*)d_in[4];

    int off = (in_sizes[5] == 1) ? 1 : 0;
    const float* W_em = (const float*)d_in[5 + off],  *b_em = (const float*)d_in[6 + off];
    const float* W_3d = (const float*)d_in[7 + off],  *b_3d = (const float*)d_in[8 + off];
    const float* Wq_e = (const float*)d_in[9 + off],  *bq_e = (const float*)d_in[10 + off];
    const float* Wk_e = (const float*)d_in[11 + off], *bk_e = (const float*)d_in[12 + off];
    const float* Wv_e = (const float*)d_in[13 + off], *bv_e = (const float*)d_in[14 + off];
    const float* Wq_d = (const float*)d_in[15 + off], *bq_d = (const float*)d_in[16 + off];
    const float* Wk_d = (const float*)d_in[17 + off], *bk_d = (const float*)d_in[18 + off];
    const float* Wv_d = (const float*)d_in[19 + off], *bv_d = (const float*)d_in[20 + off];
    const float* W_fus = (const float*)d_in[21 + off], *b_fus = (const float*)d_in[22 + off];
    const float* W_fc1 = (const float*)d_in[23 + off], *b_fc1 = (const float*)d_in[24 + off];
    const float* W_fc2 = (const float*)d_in[25 + off], *b_fc2 = (const float*)d_in[26 + off];
    const float* W_ih = (const float*)d_in[27 + off];
    const float* W_hh = (const float*)d_in[28 + off];
    const float* b_ih = (const float*)d_in[29 + off];
    const float* b_hh = (const float*)d_in[30 + off];

    float* pLE    = sym_addr(d_LE);
    float* pLD    = sym_addr(d_LD);
    float* pQe    = sym_addr(d_Qe);
    float* pQd    = sym_addr(d_Qd);
    float* pSRCe  = sym_addr(d_SRCe);
    float* pSRCd  = sym_addr(d_SRCd);
    float* pKe    = sym_addr(d_Ke);
    float* pVe    = sym_addr(d_Ve);
    float* pKd    = sym_addr(d_Kd);
    float* pVd    = sym_addr(d_Vd);
    float* pS     = sym_addr(d_S);
    float* pFeatE = sym_addr(d_FeatE);
    float* pFeatD = sym_addr(d_FeatD);
    float* pFlat  = sym_addr(d_Flat);

    const float inv_sqrt_d = 1.0f / sqrtf(128.0f);

    fill_pf<<<16, 128>>>(pf);

    launch_gemm(li_emo, W_em, pLE, b_em, 512, 128, 25, 25, 25, 128,
                512LL * 25, 1, 0, 1, 512LL * 128, 64, 1.f, 1, 0);
    launch_gemm(sp_emo, W_em, pSRCe + 128, b_em, 512, 128, 25, 25, 25, 128,
                512LL * 25, 1, 0, 1, 513LL * 128, 16, 1.f, 1, 0);
    launch_gemm(li_3d, W_3d, pLD, b_3d, 512, 128, 58, 58, 58, 128,
                512LL * 58, 1, 0, 1, 512LL * 128, 64, 1.f, 1, 0);
    launch_gemm(sp_3d, W_3d, pSRCd + 128, b_3d, 512, 128, 58, 58, 58, 128,
                512LL * 58, 1, 0, 1, 513LL * 128, 16, 1.f, 1, 0);

    launch_gemm(pSRCe, Wk_e, pKe, bk_e, 513, 128, 128, 128, 128, 128,
                513LL * 128, 1, 0, 1, 513LL * 128, 16, 1.f, 1, 0);
    launch_gemm(pSRCe, Wv_e, pVe, bv_e, 513, 128, 128, 128, 128, 128,
                513LL * 128, 1, 0, 1, 513LL * 128, 16, 1.f, 1, 0);
    launch_gemm(pLE, Wq_e, pQe, bq_e, 512, 128, 128, 128, 128, 128,
                512LL * 128, 1, 0, 1, 512LL * 128, 64, 1.f, 1, 0);
    launch_gemm(pSRCd, Wk_d, pKd, bk_d, 513, 128, 128, 128, 128, 128,
                513LL * 128, 1, 0, 1, 513LL * 128, 16, 1.f, 1, 0);
    launch_gemm(pSRCd, Wv_d, pVd, bv_d, 513, 128, 128, 128, 128, 128,
                513LL * 128, 1, 0, 1, 513LL * 128, 16, 1.f, 1, 0);
    launch_gemm(pLD, Wq_d, pQd, bq_d, 512, 128, 128, 128, 128, 128,
                512LL * 128, 1, 0, 1, 512LL * 128, 64, 1.f, 1, 0);

    launch_gemm(pQe, pKe, pS, nullptr, 512, 513, 128, 128, 128, 513,
                512LL * 128, 1, 513LL * 128, 4, 512LL * 513, 64, inv_sqrt_d, 1, 0);
    softmax_rows<<<64 * 512, 128>>>(pS, 513);
    launch_gemm(pS, pVe, pFeatE, nullptr, 512, 128, 513, 513, 128, 128,
                512LL * 513, 1, 513LL * 128, 4, 512LL * 128, 64, 1.f, 0, 0);

    launch_gemm(pQd, pKd, pS, nullptr, 512, 513, 128, 128, 128, 513,
                512LL * 128, 1, 513LL * 128, 4, 512LL * 513, 64, inv_sqrt_d, 1, 0);
    softmax_rows<<<64 * 512, 128>>>(pS, 513);
    launch_gemm(pS, pVd, pFeatD, nullptr, 512, 128, 513, 513, 128, 128,
                512LL * 513, 1, 513LL * 128, 4, 512LL * 128, 64, 1.f, 0, 0);

    launch_gemm(pFeatE, W_fus, pFlat, b_fus, 512, 128, 128, 128, 256, 64 * 128,
                512LL * 128, 1, 0, 1, 128LL, 64, 1.f, 1, 0);
    launch_gemm(pFeatD, W_fus + 128, pFlat, nullptr, 512, 128, 128, 128, 256, 64 * 128,
                512LL * 128, 1, 0, 1, 128LL, 64, 1.f, 1, 1);

    launch_gemm(pFlat, W_ih, pS, b_ih, TT, 512, 128, 128, 128, 512,
                0, 1, 0, 1, 0, 1, 1.f, 1, 0);

    lstm_kernel<<<12, 512>>>(pS, W_ih, W_hh, b_ih, b_hh);

    fc_kernel<<<64, 128>>>(W_fc1, b_fc1, W_fc2, b_fc2, (float*)d_out);
}

// round 10
// speedup vs baseline: 4.3536x; 4.3536x over previous
#include <cuda_runtime.h>
#include <math.h>
#include <stdint.h>

#define TT 32768          // 512 * 64 LSTM steps
#define D  128

// ---------------- device scratch (static: no allocations allowed) ----------------
__device__ float d_LE[64*512*128];
__device__ float d_LD[64*512*128];
__device__ float d_Qe[64*512*128];
__device__ float d_Qd[64*512*128];
__device__ float d_SRCe[16*513*128];
__device__ float d_SRCd[16*513*128];
__device__ float d_Ke[16*513*128];
__device__ float d_Ve[16*513*128];
__device__ float d_Kd[16*513*128];
__device__ float d_Vd[16*513*128];
__device__ float d_S[64*512*513];      // scores buffer; later reused as G0 [TT*512]
__device__ float d_FeatE[64*512*128];
__device__ float d_FeatD[64*512*128];
__device__ float d_Flat[TT*128];
__device__ unsigned long long d_X1[TT*128];  // layer0 -> layer1 tagged (tag,h) packets
__device__ unsigned long long d_X2[TT*128];  // layer1 -> layer2 tagged packets
__device__ float d_LastH[64*128];
// Replay determinism: X arrays are zero-init (tag 0 never matches t+1>=1); on
// graph replays stale packets hold exactly the values that get rewritten.

// ---------------- helpers ----------------
__device__ __forceinline__ uint32_t smem_u32(const void* p) {
    uint32_t a;
    asm("{ .reg .u64 t; cvta.to.shared.u64 t, %1; cvt.u32.u64 %0, t; }" : "=r"(a) : "l"(p));
    return a;
}
__device__ __forceinline__ uint32_t ctarank() {
    uint32_t r; asm("mov.u32 %0, %%cluster_ctarank;" : "=r"(r)); return r;
}
__device__ __forceinline__ uint32_t mapa_r(uint32_t addr, uint32_t rank) {
    uint32_t r; asm("mapa.shared::cluster.u32 %0, %1, %2;" : "=r"(r) : "r"(addr), "r"(rank));
    return r;
}
__device__ __forceinline__ void st_cluster_f32(uint32_t raddr, float v) {
    asm volatile("st.shared::cluster.f32 [%0], %1;" :: "r"(raddr), "f"(v) : "memory");
}
__device__ __forceinline__ void mbar_init(uint32_t addr, uint32_t cnt) {
    asm volatile("mbarrier.init.shared.b64 [%0], %1;" :: "r"(addr), "r"(cnt) : "memory");
}
__device__ __forceinline__ void mbar_arrive_cluster(uint32_t raddr) {
    asm volatile("mbarrier.arrive.release.cluster.shared::cluster.b64 _, [%0];"
                 :: "r"(raddr) : "memory");
}
__device__ __forceinline__ void mbar_wait_parity(uint32_t addr, uint32_t parity) {
    asm volatile(
        "{\n\t"
        ".reg .pred P;\n\t"
        "LAB_%=:\n\t"
        "mbarrier.try_wait.parity.acquire.cluster.shared::cta.b64 P, [%0], %1, 0x989680;\n\t"
        "@P bra DONE_%=;\n\t"
        "bra LAB_%=;\n\t"
        "DONE_%=:\n\t"
        "}" :: "r"(addr), "r"(parity) : "memory");
}
__device__ __forceinline__ void cluster_sync_() {
    asm volatile("barrier.cluster.arrive.aligned;" ::: "memory");
    asm volatile("barrier.cluster.wait.aligned;" ::: "memory");
}
__device__ __forceinline__ unsigned long long pk2(float a, float b) {
    unsigned long long r;
    asm("mov.b64 %0, {%1, %2};" : "=l"(r) : "f"(a), "f"(b));
    return r;
}
__device__ __forceinline__ void fma2(unsigned long long& acc, unsigned long long a, unsigned long long b) {
    asm("fma.rn.f32x2 %0, %1, %2, %0;" : "+l"(acc) : "l"(a), "l"(b));
}
__device__ __forceinline__ float upk_sum(unsigned long long v) {
    float lo, hi;
    asm("mov.b64 {%0, %1}, %2;" : "=f"(lo), "=f"(hi) : "l"(v));
    return lo + hi;
}
__device__ __forceinline__ unsigned long long ld_vol_global_u64(const unsigned long long* p) {
    unsigned long long v;
    asm volatile("ld.volatile.global.b64 %0, [%1];" : "=l"(v) : "l"(p) : "memory");
    return v;
}
__device__ __forceinline__ void st_vol_global_u64(unsigned long long* p, unsigned long long v) {
    asm volatile("st.volatile.global.b64 [%0], %1;" :: "l"(p), "l"(v) : "memory");
}
__device__ __forceinline__ float pkt_val(unsigned long long p) {
    return __uint_as_float((unsigned)(p >> 32));
}
__device__ __forceinline__ unsigned pkt_tag(unsigned long long p) { return (unsigned)p; }
__device__ __forceinline__ unsigned long long mk_pkt(unsigned tag, float v) {
    return ((unsigned long long)__float_as_uint(v) << 32) | (unsigned long long)tag;
}
__device__ __forceinline__ float tanh_ap(float x) {
    float y; asm("tanh.approx.f32 %0, %1;" : "=f"(y) : "f"(x)); return y;
}
__device__ __forceinline__ float sig_ap(float x) {
    return 0.5f * tanh_ap(0.5f * x) + 0.5f;
}

// ---------------- generic tiled GEMM (parallel phase) ----------------
__global__ void gemm_k(const float* __restrict__ A, const float* __restrict__ B,
                       float* __restrict__ C, const float* __restrict__ bias,
                       int M, int N, int K, int lda, int ldb, int ldc,
                       long long sA, int divA, long long sB, int divB, long long sC,
                       float alpha, int transB, int accum)
{
    int bz = blockIdx.z;
    const float* Ab = A + (long long)(bz / divA) * sA;
    const float* Bb = B + (long long)(bz / divB) * sB;
    float*       Cb = C + (long long)bz * sC;

    int m0 = blockIdx.y * 64, n0 = blockIdx.x * 64;
    int tx = threadIdx.x, ty = threadIdx.y;
    int tid = ty * 16 + tx;

    __shared__ float As[16][64];
    __shared__ float Bs[16][64];

    float acc[4][4];
#pragma unroll
    for (int i = 0; i < 4; i++)
#pragma unroll
        for (int j = 0; j < 4; j++) acc[i][j] = 0.f;

    for (int k0 = 0; k0 < K; k0 += 16) {
#pragma unroll
        for (int e = 0; e < 4; e++) {
            int idx = tid + 256 * e;
            int kk = idx & 15, m = idx >> 4;
            int gm = m0 + m, gk = k0 + kk;
            As[kk][m] = (gm < M && gk < K) ? Ab[(long long)gm * lda + gk] : 0.f;
        }
        if (transB) {
#pragma unroll
            for (int e = 0; e < 4; e++) {
                int idx = tid + 256 * e;
                int kk = idx & 15, n = idx >> 4;
                int gn = n0 + n, gk = k0 + kk;
                Bs[kk][n] = (gn < N && gk < K) ? Bb[(long long)gn * ldb + gk] : 0.f;
            }
        } else {
#pragma unroll
            for (int e = 0; e < 4; e++) {
                int idx = tid + 256 * e;
                int n = idx & 63, kk = idx >> 6;
                int gn = n0 + n, gk = k0 + kk;
                Bs[kk][n] = (gn < N && gk < K) ? Bb[(long long)gk * ldb + gn] : 0.f;
            }
        }
        __syncthreads();
#pragma unroll
        for (int kk = 0; kk < 16; kk++) {
            float4 a4 = *(const float4*)&As[kk][ty * 4];
            float4 b4 = *(const float4*)&Bs[kk][tx * 4];
            acc[0][0] += a4.x * b4.x; acc[0][1] += a4.x * b4.y; acc[0][2] += a4.x * b4.z; acc[0][3] += a4.x * b4.w;
            acc[1][0] += a4.y * b4.x; acc[1][1] += a4.y * b4.y; acc[1][2] += a4.y * b4.z; acc[1][3] += a4.y * b4.w;
            acc[2][0] += a4.z * b4.x; acc[2][1] += a4.z * b4.y; acc[2][2] += a4.z * b4.z; acc[2][3] += a4.z * b4.w;
            acc[3][0] += a4.w * b4.x; acc[3][1] += a4.w * b4.y; acc[3][2] += a4.w * b4.z; acc[3][3] += a4.w * b4.w;
        }
        __syncthreads();
    }

#pragma unroll
    for (int i = 0; i < 4; i++) {
        int gm = m0 + ty * 4 + i;
        if (gm >= M) continue;
#pragma unroll
        for (int j = 0; j < 4; j++) {
            int gn = n0 + tx * 4 + j;
            if (gn >= N) continue;
            float v = alpha * acc[i][j] + (bias ? bias[gn] : 0.f);
            long long off = (long long)gm * ldc + gn;
            Cb[off] = accum ? (Cb[off] + v) : v;
        }
    }
}

__global__ void softmax_rows(float* __restrict__ S, int n)
{
    float* row = S + (long long)blockIdx.x * n;
    int tid = threadIdx.x;
    __shared__ float red[128];

    float m = -1e30f;
    for (int i = tid; i < n; i += 128) m = fmaxf(m, row[i]);
    red[tid] = m; __syncthreads();
    for (int off = 64; off; off >>= 1) { if (tid < off) red[tid] = fmaxf(red[tid], red[tid + off]); __syncthreads(); }
    float mx = red[0]; __syncthreads();

    float s = 0.f;
    for (int i = tid; i < n; i += 128) { float e = expf(row[i] - mx); row[i] = e; s += e; }
    red[tid] = s; __syncthreads();
    for (int off = 64; off; off >>= 1) { if (tid < off) red[tid] += red[tid + off]; __syncthreads(); }
    float inv = 1.f / red[0];
    __syncthreads();
    for (int i = tid; i < n; i += 128) row[i] *= inv;
}

__global__ void fill_pf(const float* __restrict__ pf)
{
    int sb = blockIdx.x, d = threadIdx.x;
    float v = 1e-5f * pf[sb * 128 + d];
    d_SRCe[(long long)sb * 513 * 128 + d] = v;
    d_SRCd[(long long)sb * 513 * 128 + d] = v;
}

// ---------------- sequential 3-layer LSTM (R3 skeleton + fast cell + x prefetch) --
// Cluster = one layer (4 CTAs). CTA rank c owns h-indices J in [32c, 32c+32).
// Thread (j = tid>>4, s = tid&15); k-slice [8s, 8s+8). s==0 lanes run the cell,
// push h to all 4 CTAs (DSMEM) + arrive on their mbarriers (HW-sleep waits).
// x handoff: tagged u64 packets in gmem, prefetched one step ahead by tid<32.
__global__ void __launch_bounds__(512, 1) __cluster_dims__(4, 1, 1) lstm_kernel(
    const float* __restrict__ G0,     // [TT][512] = flat@W_ih0^T + b_ih0
    const float* __restrict__ W_ih,
    const float* __restrict__ W_hh,
    const float* __restrict__ b_ih,
    const float* __restrict__ b_hh)
{
    const int l   = blockIdx.x >> 2;
    const uint32_t c = ctarank();
    const int tid = threadIdx.x;
    const int j   = tid >> 4;
    const int s   = tid & 15;
    const int J   = (int)c * 32 + j;
    const bool isCell = (s == 0);

    unsigned long long whh[4][4], wih[4][4];
#pragma unroll
    for (int G = 0; G < 4; G++) {
        int R = l * 512 + G * 128 + J;
#pragma unroll
        for (int q = 0; q < 4; q++) {
            float2 w = *(const float2*)&W_hh[(long long)R * 128 + 8 * s + 2 * q];
            whh[G][q] = pk2(w.x, w.y);
        }
    }
    if (l > 0) {
#pragma unroll
        for (int G = 0; G < 4; G++) {
            int R = l * 512 + G * 128 + J;
#pragma unroll
            for (int q = 0; q < 4; q++) {
                float2 w = *(const float2*)&W_ih[(long long)R * 128 + 8 * s + 2 * q];
                wih[G][q] = pk2(w.x, w.y);
            }
        }
    } else {
#pragma unroll
        for (int G = 0; G < 4; G++)
#pragma unroll
            for (int q = 0; q < 4; q++) wih[G][q] = 0ull;
    }

    float bias[4];
#pragma unroll
    for (int G = 0; G < 4; G++) {
        int R = l * 512 + G * 128 + J;
        bias[G] = b_hh[R] + (l > 0 ? b_ih[R] : 0.f);
    }

    __shared__ float sh_h[2][128];
    __shared__ float sh_x[2][128];
    __shared__ __align__(8) unsigned long long mbar;

    if (tid < 128) { sh_h[0][tid] = 0.f; sh_h[1][tid] = 0.f; }
    const uint32_t mbar_a = smem_u32(&mbar);
    if (tid == 0) mbar_init(mbar_a, 128);
    __syncthreads();
    cluster_sync_();

    const unsigned long long* Xin  = (l == 1) ? d_X1 : d_X2;
    unsigned long long*       Xout = (l == 0) ? d_X1 : d_X2;

    float g0next[4] = {0.f, 0.f, 0.f, 0.f};
    if (l == 0 && isCell) {
#pragma unroll
        for (int G = 0; G < 4; G++) g0next[G] = __ldg(&G0[G * 128 + J]);
    }
    float cst = 0.f;

    const uint32_t h_base = smem_u32(&sh_h[0][0]);

    // x prefetch registers (tid<32, l>0): packets for current step
    unsigned long long xr0 = 0ull, xr1 = 0ull, xr2 = 0ull, xr3 = 0ull;

    for (int t = 0; t < TT; t++) {
        if (l > 0) {
            if (tid < 32) {
                const unsigned want = (unsigned)(t + 1);
                const unsigned long long* xp = Xin + (long long)t * 128 + 4 * tid;
                for (;;) {
                    unsigned mt = pkt_tag(xr0) & pkt_tag(xr1) & pkt_tag(xr2) & pkt_tag(xr3);
                    unsigned ot = pkt_tag(xr0) | pkt_tag(xr1) | pkt_tag(xr2) | pkt_tag(xr3);
                    if (mt == want && ot == want) break;
                    __nanosleep(40);
                    xr0 = ld_vol_global_u64(xp + 0);
                    xr1 = ld_vol_global_u64(xp + 1);
                    xr2 = ld_vol_global_u64(xp + 2);
                    xr3 = ld_vol_global_u64(xp + 3);
                }
                float* xb = &sh_x[t & 1][4 * tid];
                xb[0] = pkt_val(xr0); xb[1] = pkt_val(xr1);
                xb[2] = pkt_val(xr2); xb[3] = pkt_val(xr3);
                // prefetch step t+1's packets (verified next iteration)
                if (t + 1 < TT) {
                    const unsigned long long* xn = Xin + (long long)(t + 1) * 128 + 4 * tid;
                    xr0 = ld_vol_global_u64(xn + 0);
                    xr1 = ld_vol_global_u64(xn + 1);
                    xr2 = ld_vol_global_u64(xn + 2);
                    xr3 = ld_vol_global_u64(xn + 3);
                }
            }
            __syncthreads();
        }

        const int rb = (t & 1) ^ 1;   // read buffer (h from step t-1)

        unsigned long long acc[4] = {0ull, 0ull, 0ull, 0ull};
        {
            float4 h0 = *(const float4*)&sh_h[rb][8 * s];
            float4 h1 = *(const float4*)&sh_h[rb][8 * s + 4];
            unsigned long long hp[4] = { pk2(h0.x, h0.y), pk2(h0.z, h0.w),
                                         pk2(h1.x, h1.y), pk2(h1.z, h1.w) };
#pragma unroll
            for (int G = 0; G < 4; G++) {
                fma2(acc[G], whh[G][0], hp[0]);
                fma2(acc[G], whh[G][1], hp[1]);
                fma2(acc[G], whh[G][2], hp[2]);
                fma2(acc[G], whh[G][3], hp[3]);
            }
            if (l > 0) {
                float4 x0 = *(const float4*)&sh_x[t & 1][8 * s];
                float4 x1 = *(const float4*)&sh_x[t & 1][8 * s + 4];
                unsigned long long xp4[4] = { pk2(x0.x, x0.y), pk2(x0.z, x0.w),
                                              pk2(x1.x, x1.y), pk2(x1.z, x1.w) };
#pragma unroll
                for (int G = 0; G < 4; G++) {
                    fma2(acc[G], wih[G][0], xp4[0]);
                    fma2(acc[G], wih[G][1], xp4[1]);
                    fma2(acc[G], wih[G][2], xp4[2]);
                    fma2(acc[G], wih[G][3], xp4[3]);
                }
            }
        }
        float g[4];
#pragma unroll
        for (int G = 0; G < 4; G++) g[G] = upk_sum(acc[G]);

#pragma unroll
        for (int m = 1; m < 16; m <<= 1) {
#pragma unroll
            for (int G = 0; G < 4; G++)
                g[G] += __shfl_xor_sync(0xffffffffu, g[G], m);
        }

        if (isCell) {
            float gi = g[0] + bias[0] + g0next[0];
            float gf = g[1] + bias[1] + g0next[1];
            float gc = g[2] + bias[2] + g0next[2];
            float go = g[3] + bias[3] + g0next[3];

            float si = sig_ap(gi), sf = sig_ap(gf), so = sig_ap(go);
            cst = sf * cst + si * tanh_ap(gc);
            float h = so * tanh_ap(cst);

            uint32_t laddr = h_base + (uint32_t)(((t & 1) * 128 + J) * 4);
#pragma unroll
            for (uint32_t r = 0; r < 4; r++)
                st_cluster_f32(mapa_r(laddr, r), h);

            if (l < 2) st_vol_global_u64(&Xout[(long long)t * 128 + J],
                                         mk_pkt((unsigned)(t + 1), h));
            else if (t >= TT - 64) d_LastH[(t - (TT - 64)) * 128 + J] = h;

            if (l == 0 && t + 1 < TT) {
#pragma unroll
                for (int G = 0; G < 4; G++)
                    g0next[G] = __ldg(&G0[(long long)(t + 1) * 512 + G * 128 + J]);
            }

#pragma unroll
            for (uint32_t r = 0; r < 4; r++)
                mbar_arrive_cluster(mapa_r(mbar_a, r));
        }

        mbar_wait_parity(mbar_a, (uint32_t)(t & 1));
    }
    cluster_sync_();
}

__global__ void fc_kernel(const float* __restrict__ W1, const float* __restrict__ b1,
                          const float* __restrict__ W2, const float* __restrict__ b2,
                          float* __restrict__ out)
{
    int b = blockIdx.x, tid = threadIdx.x;
    __shared__ float sh[128];
    __shared__ float red[128];
    sh[tid] = d_LastH[b * 128 + tid];
    __syncthreads();
    float s = b1[tid];
    const float* w = W1 + tid * 128;
#pragma unroll 4
    for (int k = 0; k < 128; k++) s += w[k] * sh[k];
    s = fmaxf(s, 0.f) * W2[tid];
    red[tid] = s; __syncthreads();
    for (int off = 64; off; off >>= 1) { if (tid < off) red[tid] += red[tid + off]; __syncthreads(); }
    if (tid == 0) out[b] = 1.f / (1.f + expf(-(red[0] + b2[0])));
}

static void launch_gemm(const float* A, const float* B, float* C, const float* bias,
                        int M, int N, int K, int lda, int ldb, int ldc,
                        long long sA, int divA, long long sB, int divB, long long sC,
                        int batch, float alpha, int transB, int accum)
{
    dim3 grid((N + 63) / 64, (M + 63) / 64, batch), blk(16, 16);
    gemm_k<<<grid, blk>>>(A, B, C, bias, M, N, K, lda, ldb, ldc,
                          sA, divA, sB, divB, sC, alpha, transB, accum);
}

template <typename T>
static float* sym_addr(const T& s)
{
    void* p = nullptr;
    cudaGetSymbolAddress(&p, s);
    return (float*)p;
}

extern "C" void kernel_launch(void* const* d_in, const int* in_sizes, int n_in,
                              void* d_out, int out_size)
{
    const float* sp_emo = (const float*)d_in[0];
    const float* li_emo = (const float*)d_in[1];
    const float* sp_3d  = (const float*)d_in[2];
    const float* li_3d  = (const float*)d_in[3];
    const float* pf     = (const float*)d_in[4];

    int off = (in_sizes[5] == 1) ? 1 : 0;
    const float* W_em = (const float*)d_in[5 + off],  *b_em = (const float*)d_in[6 + off];
    const float* W_3d = (const float*)d_in[7 + off],  *b_3d = (const float*)d_in[8 + off];
    const float* Wq_e = (const float*)d_in[9 + off],  *bq_e = (const float*)d_in[10 + off];
    const float* Wk_e = (const float*)d_in[11 + off], *bk_e = (const float*)d_in[12 + off];
    const float* Wv_e = (const float*)d_in[13 + off], *bv_e = (const float*)d_in[14 + off];
    const float* Wq_d = (const float*)d_in[15 + off], *bq_d = (const float*)d_in[16 + off];
    const float* Wk_d = (const float*)d_in[17 + off], *bk_d = (const float*)d_in[18 + off];
    const float* Wv_d = (const float*)d_in[19 + off], *bv_d = (const float*)d_in[20 + off];
    const float* W_fus = (const float*)d_in[21 + off], *b_fus = (const float*)d_in[22 + off];
    const float* W_fc1 = (const float*)d_in[23 + off], *b_fc1 = (const float*)d_in[24 + off];
    const float* W_fc2 = (const float*)d_in[25 + off], *b_fc2 = (const float*)d_in[26 + off];
    const float* W_ih = (const float*)d_in[27 + off];
    const float* W_hh = (const float*)d_in[28 + off];
    const float* b_ih = (const float*)d_in[29 + off];
    const float* b_hh = (const float*)d_in[30 + off];

    float* pLE    = sym_addr(d_LE);
    float* pLD    = sym_addr(d_LD);
    float* pQe    = sym_addr(d_Qe);
    float* pQd    = sym_addr(d_Qd);
    float* pSRCe  = sym_addr(d_SRCe);
    float* pSRCd  = sym_addr(d_SRCd);
    float* pKe    = sym_addr(d_Ke);
    float* pVe    = sym_addr(d_Ve);
    float* pKd    = sym_addr(d_Kd);
    float* pVd    = sym_addr(d_Vd);
    float* pS     = sym_addr(d_S);
    float* pFeatE = sym_addr(d_FeatE);
    float* pFeatD = sym_addr(d_FeatD);
    float* pFlat  = sym_addr(d_Flat);

    const float inv_sqrt_d = 1.0f / sqrtf(128.0f);

    fill_pf<<<16, 128>>>(pf);

    launch_gemm(li_emo, W_em, pLE, b_em, 512, 128, 25, 25, 25, 128,
                512LL * 25, 1, 0, 1, 512LL * 128, 64, 1.f, 1, 0);
    launch_gemm(sp_emo, W_em, pSRCe + 128, b_em, 512, 128, 25, 25, 25, 128,
                512LL * 25, 1, 0, 1, 513LL * 128, 16, 1.f, 1, 0);
    launch_gemm(li_3d, W_3d, pLD, b_3d, 512, 128, 58, 58, 58, 128,
                512LL * 58, 1, 0, 1, 512LL * 128, 64, 1.f, 1, 0);
    launch_gemm(sp_3d, W_3d, pSRCd + 128, b_3d, 512, 128, 58, 58, 58, 128,
                512LL * 58, 1, 0, 1, 513LL * 128, 16, 1.f, 1, 0);

    launch_gemm(pSRCe, Wk_e, pKe, bk_e, 513, 128, 128, 128, 128, 128,
                513LL * 128, 1, 0, 1, 513LL * 128, 16, 1.f, 1, 0);
    launch_gemm(pSRCe, Wv_e, pVe, bv_e, 513, 128, 128, 128, 128, 128,
                513LL * 128, 1, 0, 1, 513LL * 128, 16, 1.f, 1, 0);
    launch_gemm(pLE, Wq_e, pQe, bq_e, 512, 128, 128, 128, 128, 128,
                512LL * 128, 1, 0, 1, 512LL * 128, 64, 1.f, 1, 0);
    launch_gemm(pSRCd, Wk_d, pKd, bk_d, 513, 128, 128, 128, 128, 128,
                513LL * 128, 1, 0, 1, 513LL * 128, 16, 1.f, 1, 0);
    launch_gemm(pSRCd, Wv_d, pVd, bv_d, 513, 128, 128, 128, 128, 128,
                513LL * 128, 1, 0, 1, 513LL * 128, 16, 1.f, 1, 0);
    launch_gemm(pLD, Wq_d, pQd, bq_d, 512, 128, 128, 128, 128, 128,
                512LL * 128, 1, 0, 1, 512LL * 128, 64, 1.f, 1, 0);

    launch_gemm(pQe, pKe, pS, nullptr, 512, 513, 128, 128, 128, 513,
                512LL * 128, 1, 513LL * 128, 4, 512LL * 513, 64, inv_sqrt_d, 1, 0);
    softmax_rows<<<64 * 512, 128>>>(pS, 513);
    launch_gemm(pS, pVe, pFeatE, nullptr, 512, 128, 513, 513, 128, 128,
                512LL * 513, 1, 513LL * 128, 4, 512LL * 128, 64, 1.f, 0, 0);

    launch_gemm(pQd, pKd, pS, nullptr, 512, 513, 128, 128, 128, 513,
                512LL * 128, 1, 513LL * 128, 4, 512LL * 513, 64, inv_sqrt_d, 1, 0);
    softmax_rows<<<64 * 512, 128>>>(pS, 513);
    launch_gemm(pS, pVd, pFeatD, nullptr, 512, 128, 513, 513, 128, 128,
                512LL * 513, 1, 513LL * 128, 4, 512LL * 128, 64, 1.f, 0, 0);

    launch_gemm(pFeatE, W_fus, pFlat, b_fus, 512, 128, 128, 128, 256, 64 * 128,
                512LL * 128, 1, 0, 1, 128LL, 64, 1.f, 1, 0);
    launch_gemm(pFeatD, W_fus + 128, pFlat, nullptr, 512, 128, 128, 128, 256, 64 * 128,
                512LL * 128, 1, 0, 1, 128LL, 64, 1.f, 1, 1);

    launch_gemm(pFlat, W_ih, pS, b_ih, TT, 512, 128, 128, 128, 512,
                0, 1, 0, 1, 0, 1, 1.f, 1, 0);

    lstm_kernel<<<12, 512>>>(pS, W_ih, W_hh, b_ih, b_hh);

    fc_kernel<<<64, 128>>>(W_fc1, b_fc1, W_fc2, b_fc2, (float*)d_out);
}